// round 2
// baseline (speedup 1.0000x reference)
#include <cuda_runtime.h>
#include <math.h>

#define BB 64      // batch
#define TT 512     // seq len
#define FF 128     // input features
#define HH 512     // hidden
#define G4 2048    // 4*H
#define NR 32768   // B*T

// ---------------- scratch (device globals; no allocations) ----------------
__device__ float g_xw[(size_t)NR * G4];        // [t][b][4H]  (256 MB)
__device__ float g_h1[(size_t)TT * HH * BB];   // [t][k][b]   (64 MB)
__device__ float g_h2[(size_t)TT * HH * BB];   // [t][k][b]
__device__ float g_hT[2][HH * BB];             // ping-pong h state, [k][b]
__device__ float g_cT[HH * BB];                // c state, [k][b]
__device__ float g_scale[2 * HH];              // BN folded scale per layer
__device__ float g_shift[2 * HH];              // BN folded shift per layer
__device__ unsigned g_bar[2];                  // grid barrier counters (one per layer)

// ---------------- zero h/c state + barrier counters ----------------
__global__ void zero_state() {
    int idx = blockIdx.x * blockDim.x + threadIdx.x;
    if (idx < HH * BB) {
        g_hT[0][idx] = 0.f;
        g_hT[1][idx] = 0.f;
        g_cT[idx]    = 0.f;
    }
    if (idx < 2) g_bar[idx] = 0u;
}

// ---------------- GEMM 1: g_xw[t*64+b][n] = x[b*T+t][:] @ Wx1 + b1 ----------------
__global__ __launch_bounds__(256) void gemm_xw1(const float* __restrict__ x,
                                                const float* __restrict__ W,
                                                const float* __restrict__ bias) {
    __shared__ __align__(16) float As[16][68];
    __shared__ __align__(16) float Bs[16][68];
    const int tid = threadIdx.x;
    const int m0 = blockIdx.y * 64;
    const int n0 = blockIdx.x * 64;
    const int tm = (tid >> 4) << 2;
    const int tn = (tid & 15) << 2;
    float acc[4][4] = {};
    for (int k0 = 0; k0 < FF; k0 += 16) {
        {
            int m = tid >> 2, q = tid & 3;
            float4 v = *reinterpret_cast<const float4*>(x + (size_t)(m0 + m) * FF + k0 + q * 4);
            As[q * 4 + 0][m] = v.x; As[q * 4 + 1][m] = v.y;
            As[q * 4 + 2][m] = v.z; As[q * 4 + 3][m] = v.w;
        }
        {
            int k = tid >> 4, c = (tid & 15) << 2;
            float4 v = *reinterpret_cast<const float4*>(W + (size_t)(k0 + k) * G4 + n0 + c);
            Bs[k][c] = v.x; Bs[k][c + 1] = v.y; Bs[k][c + 2] = v.z; Bs[k][c + 3] = v.w;
        }
        __syncthreads();
#pragma unroll
        for (int k = 0; k < 16; k++) {
            float4 a = *reinterpret_cast<const float4*>(&As[k][tm]);
            float4 b = *reinterpret_cast<const float4*>(&Bs[k][tn]);
            acc[0][0] += a.x * b.x; acc[0][1] += a.x * b.y; acc[0][2] += a.x * b.z; acc[0][3] += a.x * b.w;
            acc[1][0] += a.y * b.x; acc[1][1] += a.y * b.y; acc[1][2] += a.y * b.z; acc[1][3] += a.y * b.w;
            acc[2][0] += a.z * b.x; acc[2][1] += a.z * b.y; acc[2][2] += a.z * b.z; acc[2][3] += a.z * b.w;
            acc[3][0] += a.w * b.x; acc[3][1] += a.w * b.y; acc[3][2] += a.w * b.z; acc[3][3] += a.w * b.w;
        }
        __syncthreads();
    }
    float4 bv = *reinterpret_cast<const float4*>(bias + n0 + tn);
#pragma unroll
    for (int i = 0; i < 4; i++) {
        int r = m0 + tm + i;                          // r = b*T + t
        int orow = ((r & (TT - 1)) << 6) + (r >> 9);  // t*64 + b
        float4 o;
        o.x = acc[i][0] + bv.x; o.y = acc[i][1] + bv.y;
        o.z = acc[i][2] + bv.z; o.w = acc[i][3] + bv.w;
        *reinterpret_cast<float4*>(g_xw + (size_t)orow * G4 + n0 + tn) = o;
    }
}

// ---------------- GEMM 2: g_xw[t*64+b][n] = bn(h1)[t,b,:] @ Wx2 + b2 ----------------
__global__ __launch_bounds__(256) void gemm_xw2(const float* __restrict__ W,
                                                const float* __restrict__ bias) {
    __shared__ __align__(16) float As[16][68];
    __shared__ __align__(16) float Bs[16][68];
    const int tid = threadIdx.x;
    const int t = blockIdx.y;
    const int n0 = blockIdx.x * 64;
    const int tm = (tid >> 4) << 2;
    const int tn = (tid & 15) << 2;
    const float* Ab = g_h1 + (size_t)t * (HH * BB);
    float acc[4][4] = {};
    for (int k0 = 0; k0 < HH; k0 += 16) {
        {
            int b = tid & 63, kk = tid >> 6;
#pragma unroll
            for (int s = 0; s < 4; s++) {
                int k = kk * 4 + s;
                float v = Ab[(size_t)(k0 + k) * BB + b];
                As[k][b] = v * g_scale[k0 + k] + g_shift[k0 + k];
            }
        }
        {
            int k = tid >> 4, c = (tid & 15) << 2;
            float4 v = *reinterpret_cast<const float4*>(W + (size_t)(k0 + k) * G4 + n0 + c);
            Bs[k][c] = v.x; Bs[k][c + 1] = v.y; Bs[k][c + 2] = v.z; Bs[k][c + 3] = v.w;
        }
        __syncthreads();
#pragma unroll
        for (int k = 0; k < 16; k++) {
            float4 a = *reinterpret_cast<const float4*>(&As[k][tm]);
            float4 b = *reinterpret_cast<const float4*>(&Bs[k][tn]);
            acc[0][0] += a.x * b.x; acc[0][1] += a.x * b.y; acc[0][2] += a.x * b.z; acc[0][3] += a.x * b.w;
            acc[1][0] += a.y * b.x; acc[1][1] += a.y * b.y; acc[1][2] += a.y * b.z; acc[1][3] += a.y * b.w;
            acc[2][0] += a.z * b.x; acc[2][1] += a.z * b.y; acc[2][2] += a.z * b.z; acc[2][3] += a.z * b.w;
            acc[3][0] += a.w * b.x; acc[3][1] += a.w * b.y; acc[3][2] += a.w * b.z; acc[3][3] += a.w * b.w;
        }
        __syncthreads();
    }
    float4 bv = *reinterpret_cast<const float4*>(bias + n0 + tn);
#pragma unroll
    for (int i = 0; i < 4; i++) {
        int orow = t * 64 + tm + i;
        float4 o;
        o.x = acc[i][0] + bv.x; o.y = acc[i][1] + bv.y;
        o.z = acc[i][2] + bv.z; o.w = acc[i][3] + bv.w;
        *reinterpret_cast<float4*>(g_xw + (size_t)orow * G4 + n0 + tn) = o;
    }
}

// ---------------- persistent LSTM layer: loops all 512 timesteps in one kernel ------
// 128 blocks (one wave, all resident) x 256 threads. Block owns 4 hidden units:
// 16 z-columns (4 gates x 4 units), all 64 batches.
// Cross-block h state via L2 (__ldcg) + software grid barrier per step.
__global__ __launch_bounds__(256) void lstm_layer(const float* __restrict__ Wh, int layer) {
    __shared__ __align__(16) float h_s[64][68];  // [k][b] chunk
    __shared__ float w_s[64][16];                // [k][j]
    __shared__ float zb[16][68];                 // [j][b]
    const int tid = threadIdx.x;
    const int j = tid & 15, bg = tid >> 4;       // j: col-in-block, bg: 4-batch group
    const int u0 = blockIdx.x << 2;
    const int col = (j >> 2) * HH + u0 + (j & 3);
    float* hseq = layer ? g_h2 : g_h1;
    unsigned* bar = &g_bar[layer];
    const int u2 = tid >> 6, b = tid & 63;
    const size_t sidx = (size_t)(u0 + u2) * BB + b;
    float c_reg = 0.f;                           // c state is block-private -> registers

    // preload Wh slice for this block's 16 columns: 512 k x 16 j = 32KB; keep in smem?
    // (512x16 floats = 32KB; reload per chunk instead to keep smem small and reuse loop)
    for (int t = 0; t < TT; t++) {
        const float* hin = g_hT[t & 1];
        float* hout = g_hT[(t & 1) ^ 1];

        float acc0, acc1, acc2, acc3;
        {
            const float* xw = g_xw + (size_t)t * (BB * G4) + col;
            acc0 = xw[(size_t)(bg * 4 + 0) * G4];
            acc1 = xw[(size_t)(bg * 4 + 1) * G4];
            acc2 = xw[(size_t)(bg * 4 + 2) * G4];
            acc3 = xw[(size_t)(bg * 4 + 3) * G4];
        }
        for (int k0 = 0; k0 < HH; k0 += 64) {
#pragma unroll
            for (int i = 0; i < 16; i++) {
                int lin = tid + i * 256;
                // L2-coherent load: h written by other blocks (L1 is stale inside a launch)
                h_s[lin >> 6][lin & 63] = __ldcg(hin + (size_t)(k0 + (lin >> 6)) * BB + (lin & 63));
            }
#pragma unroll
            for (int i = 0; i < 4; i++) {
                int lin = tid + i * 256;
                int jj = lin & 15, k = lin >> 4;
                w_s[k][jj] = Wh[(size_t)(k0 + k) * G4 + (jj >> 2) * HH + u0 + (jj & 3)];
            }
            __syncthreads();
#pragma unroll
            for (int k = 0; k < 64; k++) {
                float4 hv = *reinterpret_cast<const float4*>(&h_s[k][bg << 2]);
                float wv = w_s[k][j];
                acc0 += hv.x * wv; acc1 += hv.y * wv;
                acc2 += hv.z * wv; acc3 += hv.w * wv;
            }
            __syncthreads();
        }
        zb[j][(bg << 2) + 0] = acc0; zb[j][(bg << 2) + 1] = acc1;
        zb[j][(bg << 2) + 2] = acc2; zb[j][(bg << 2) + 3] = acc3;
        __syncthreads();
        {
            float zi = zb[u2][b], zf = zb[4 + u2][b], zg = zb[8 + u2][b], zo = zb[12 + u2][b];
            float ig = 1.f / (1.f + expf(-zi));
            float fg = 1.f / (1.f + expf(-zf));
            float og = 1.f / (1.f + expf(-zo));
            float gg = tanhf(zg);
            c_reg = fg * c_reg + ig * gg;
            float hn = og * tanhf(c_reg);
            hout[sidx] = hn;
            hseq[(size_t)t * (HH * BB) + sidx] = hn;
        }
        // -------- grid barrier: all blocks must finish writing hout before next step ----
        __threadfence();
        __syncthreads();
        if (tid == 0) {
            atomicAdd(bar, 1u);
            unsigned target = (unsigned)(t + 1) * 128u;
            while (*(volatile unsigned*)bar < target) { }
        }
        __syncthreads();
    }
}

// ---------------- BN stats (training mode), folded scale/shift, deterministic -------
__global__ __launch_bounds__(256) void bn_stats(int layer, const float* __restrict__ gamma,
                                                const float* __restrict__ beta) {
    const float* h = layer ? g_h2 : g_h1;
    const int kf = blockIdx.x;
    const int tid = threadIdx.x;
    float s = 0.f, ss = 0.f;
    for (int lin = tid; lin < NR; lin += 256) {
        float v = h[(size_t)(lin >> 6) * (HH * BB) + (size_t)kf * BB + (lin & 63)];
        s += v; ss += v * v;
    }
    __shared__ float rs[256], rq[256];
    rs[tid] = s; rq[tid] = ss;
    __syncthreads();
    for (int off = 128; off > 0; off >>= 1) {
        if (tid < off) { rs[tid] += rs[tid + off]; rq[tid] += rq[tid + off]; }
        __syncthreads();
    }
    if (tid == 0) {
        float mean = rs[0] * (1.f / 32768.f);
        float var = rq[0] * (1.f / 32768.f) - mean * mean;
        float rstd = rsqrtf(var + 1e-5f);
        float sc = rstd * gamma[kf];
        g_scale[layer * HH + kf] = sc;
        g_shift[layer * HH + kf] = beta[kf] - mean * sc;
    }
}

// ---------------- Dense head: out[b*T+t] = relu(bn(h2) @ Wd1 + bd1) @ Wd2 + bd2 -----
__global__ __launch_bounds__(256) void dense_out(const float* __restrict__ Wd1,
                                                 const float* __restrict__ bd1,
                                                 const float* __restrict__ Wd2,
                                                 const float* __restrict__ bd2,
                                                 float* __restrict__ out) {
    __shared__ float hs[64][68];
    __shared__ float ws[64][16];
    __shared__ float sp[4][64];
    const int t = blockIdx.x, tid = threadIdx.x;
    const int b = tid & 63, jg = tid >> 6;
    float a0 = 0.f, a1 = 0.f, a2 = 0.f, a3 = 0.f;
    for (int k0 = 0; k0 < HH; k0 += 64) {
#pragma unroll
        for (int i = 0; i < 16; i++) {
            int lin = tid + i * 256; int k = lin >> 6, bb = lin & 63;
            float v = g_h2[(size_t)t * (HH * BB) + (size_t)(k0 + k) * BB + bb];
            hs[k][bb] = v * g_scale[HH + k0 + k] + g_shift[HH + k0 + k];
        }
#pragma unroll
        for (int i = 0; i < 4; i++) {
            int lin = tid + i * 256; int jj = lin & 15, k = lin >> 4;
            ws[k][jj] = Wd1[(size_t)(k0 + k) * 16 + jj];
        }
        __syncthreads();
#pragma unroll
        for (int k = 0; k < 64; k++) {
            float hv = hs[k][b];
            a0 += hv * ws[k][jg * 4 + 0];
            a1 += hv * ws[k][jg * 4 + 1];
            a2 += hv * ws[k][jg * 4 + 2];
            a3 += hv * ws[k][jg * 4 + 3];
        }
        __syncthreads();
    }
    float p = fmaxf(a0 + bd1[jg * 4 + 0], 0.f) * Wd2[jg * 4 + 0]
            + fmaxf(a1 + bd1[jg * 4 + 1], 0.f) * Wd2[jg * 4 + 1]
            + fmaxf(a2 + bd1[jg * 4 + 2], 0.f) * Wd2[jg * 4 + 2]
            + fmaxf(a3 + bd1[jg * 4 + 3], 0.f) * Wd2[jg * 4 + 3];
    sp[jg][b] = p;
    __syncthreads();
    if (tid < 64) {
        out[(size_t)tid * TT + t] = sp[0][tid] + sp[1][tid] + sp[2][tid] + sp[3][tid] + bd2[0];
    }
}

// ---------------- launch (9 graph nodes total) ----------------
extern "C" void kernel_launch(void* const* d_in, const int* in_sizes, int n_in,
                              void* d_out, int out_size) {
    const float* x   = (const float*)d_in[0];
    const float* Wx1 = (const float*)d_in[1];
    const float* Wh1 = (const float*)d_in[2];
    const float* b1  = (const float*)d_in[3];
    const float* g1  = (const float*)d_in[4];
    const float* be1 = (const float*)d_in[5];
    const float* Wx2 = (const float*)d_in[6];
    const float* Wh2 = (const float*)d_in[7];
    const float* b2  = (const float*)d_in[8];
    const float* g2  = (const float*)d_in[9];
    const float* be2 = (const float*)d_in[10];
    const float* Wd1 = (const float*)d_in[11];
    const float* bd1 = (const float*)d_in[12];
    const float* Wd2 = (const float*)d_in[13];
    const float* bd2 = (const float*)d_in[14];
    float* out = (float*)d_out;

    zero_state<<<64, 512>>>();
    gemm_xw1<<<dim3(32, 512), 256>>>(x, Wx1, b1);
    lstm_layer<<<128, 256>>>(Wh1, 0);
    bn_stats<<<512, 256>>>(0, g1, be1);
    gemm_xw2<<<dim3(32, 512), 256>>>(Wx2, b2);
    zero_state<<<64, 512>>>();
    lstm_layer<<<128, 256>>>(Wh2, 1);
    bn_stats<<<512, 256>>>(1, g2, be2);
    dense_out<<<512, 256>>>(Wd1, bd1, Wd2, bd2, out);
}

// round 4
// speedup vs baseline: 1.0880x; 1.0880x over previous
#include <cuda_runtime.h>
#include <math.h>

#define BB 64      // batch
#define TT 512     // seq len
#define FF 128     // input features
#define HH 512     // hidden
#define G4 2048    // 4*H
#define NR 32768   // B*T

// ---------------- scratch (device globals; no allocations) ----------------
__device__ float g_xw[(size_t)NR * G4];        // [t][b][4H]  (256 MB)
__device__ float g_h1[(size_t)TT * HH * BB];   // [t][k][b]   (64 MB)
__device__ float g_h2[(size_t)TT * HH * BB];   // [t][k][b]
__device__ float g_hT[2][HH * BB];             // ping-pong h state, [k][b]
__device__ float g_scale[2 * HH];              // BN folded scale per layer
__device__ float g_shift[2 * HH];              // BN folded shift per layer
__device__ unsigned g_bar[2];                  // grid barrier counters (one per layer)

// ---------------- packed f32x2 helpers (sm_103a dual-FMA path) ----------------
__device__ __forceinline__ unsigned long long pack2(float lo, float hi) {
    unsigned long long r;
    asm("mov.b64 %0, {%1, %2};" : "=l"(r) : "f"(lo), "f"(hi));
    return r;
}
__device__ __forceinline__ unsigned long long ffma2(unsigned long long a,
                                                    unsigned long long b,
                                                    unsigned long long c) {
    unsigned long long d;
    asm("fma.rn.f32x2 %0, %1, %2, %3;" : "=l"(d) : "l"(a), "l"(b), "l"(c));
    return d;
}
__device__ __forceinline__ float2 unpack2(unsigned long long v) {
    float2 f;
    asm("mov.b64 {%0, %1}, %2;" : "=f"(f.x), "=f"(f.y) : "l"(v));
    return f;
}
__device__ __forceinline__ void cp16(unsigned dst, const float* src) {
    asm volatile("cp.async.cg.shared.global [%0], [%1], 16;" :: "r"(dst), "l"(src));
}

// ---------------- zero h state + barrier counters ----------------
__global__ void zero_state() {
    int idx = blockIdx.x * blockDim.x + threadIdx.x;
    if (idx < HH * BB) {
        g_hT[0][idx] = 0.f;
        g_hT[1][idx] = 0.f;
    }
    if (idx < 2) g_bar[idx] = 0u;
}

// ---------------- GEMM 1: g_xw[t*64+b][n] = x[b*T+t][:] @ Wx1 + b1 ----------------
__global__ __launch_bounds__(256) void gemm_xw1(const float* __restrict__ x,
                                                const float* __restrict__ W,
                                                const float* __restrict__ bias) {
    __shared__ __align__(16) float As[16][68];
    __shared__ __align__(16) float Bs[16][68];
    const int tid = threadIdx.x;
    const int m0 = blockIdx.y * 64;
    const int n0 = blockIdx.x * 64;
    const int tm = (tid >> 4) << 2;
    const int tn = (tid & 15) << 2;
    unsigned long long accL[4] = {}, accH[4] = {};
    for (int k0 = 0; k0 < FF; k0 += 16) {
        {
            int m = tid >> 2, q = tid & 3;
            float4 v = *reinterpret_cast<const float4*>(x + (size_t)(m0 + m) * FF + k0 + q * 4);
            As[q * 4 + 0][m] = v.x; As[q * 4 + 1][m] = v.y;
            As[q * 4 + 2][m] = v.z; As[q * 4 + 3][m] = v.w;
        }
        {
            int k = tid >> 4, c = (tid & 15) << 2;
            float4 v = *reinterpret_cast<const float4*>(W + (size_t)(k0 + k) * G4 + n0 + c);
            Bs[k][c] = v.x; Bs[k][c + 1] = v.y; Bs[k][c + 2] = v.z; Bs[k][c + 3] = v.w;
        }
        __syncthreads();
#pragma unroll
        for (int k = 0; k < 16; k++) {
            float4 a = *reinterpret_cast<const float4*>(&As[k][tm]);
            ulonglong2 bv = *reinterpret_cast<const ulonglong2*>(&Bs[k][tn]);
            unsigned long long a0 = pack2(a.x, a.x), a1 = pack2(a.y, a.y);
            unsigned long long a2 = pack2(a.z, a.z), a3 = pack2(a.w, a.w);
            accL[0] = ffma2(a0, bv.x, accL[0]); accH[0] = ffma2(a0, bv.y, accH[0]);
            accL[1] = ffma2(a1, bv.x, accL[1]); accH[1] = ffma2(a1, bv.y, accH[1]);
            accL[2] = ffma2(a2, bv.x, accL[2]); accH[2] = ffma2(a2, bv.y, accH[2]);
            accL[3] = ffma2(a3, bv.x, accL[3]); accH[3] = ffma2(a3, bv.y, accH[3]);
        }
        __syncthreads();
    }
    float4 bvb = *reinterpret_cast<const float4*>(bias + n0 + tn);
#pragma unroll
    for (int i = 0; i < 4; i++) {
        int r = m0 + tm + i;                          // r = b*T + t
        int orow = ((r & (TT - 1)) << 6) + (r >> 9);  // t*64 + b
        float2 lo = unpack2(accL[i]), hi = unpack2(accH[i]);
        float4 o;
        o.x = lo.x + bvb.x; o.y = lo.y + bvb.y;
        o.z = hi.x + bvb.z; o.w = hi.y + bvb.w;
        *reinterpret_cast<float4*>(g_xw + (size_t)orow * G4 + n0 + tn) = o;
    }
}

// ---------------- GEMM 2: g_xw[t*64+b][n] = bn(h1)[t,b,:] @ Wx2 + b2 ----------------
__global__ __launch_bounds__(256) void gemm_xw2(const float* __restrict__ W,
                                                const float* __restrict__ bias) {
    __shared__ __align__(16) float As[16][68];
    __shared__ __align__(16) float Bs[16][68];
    const int tid = threadIdx.x;
    const int t = blockIdx.y;
    const int n0 = blockIdx.x * 64;
    const int tm = (tid >> 4) << 2;
    const int tn = (tid & 15) << 2;
    const float* Ab = g_h1 + (size_t)t * (HH * BB);
    unsigned long long accL[4] = {}, accH[4] = {};
    for (int k0 = 0; k0 < HH; k0 += 16) {
        {
            int b = tid & 63, kk = tid >> 6;
#pragma unroll
            for (int s = 0; s < 4; s++) {
                int k = kk * 4 + s;
                float v = Ab[(size_t)(k0 + k) * BB + b];
                As[k][b] = v * g_scale[k0 + k] + g_shift[k0 + k];
            }
        }
        {
            int k = tid >> 4, c = (tid & 15) << 2;
            float4 v = *reinterpret_cast<const float4*>(W + (size_t)(k0 + k) * G4 + n0 + c);
            Bs[k][c] = v.x; Bs[k][c + 1] = v.y; Bs[k][c + 2] = v.z; Bs[k][c + 3] = v.w;
        }
        __syncthreads();
#pragma unroll
        for (int k = 0; k < 16; k++) {
            float4 a = *reinterpret_cast<const float4*>(&As[k][tm]);
            ulonglong2 bv = *reinterpret_cast<const ulonglong2*>(&Bs[k][tn]);
            unsigned long long a0 = pack2(a.x, a.x), a1 = pack2(a.y, a.y);
            unsigned long long a2 = pack2(a.z, a.z), a3 = pack2(a.w, a.w);
            accL[0] = ffma2(a0, bv.x, accL[0]); accH[0] = ffma2(a0, bv.y, accH[0]);
            accL[1] = ffma2(a1, bv.x, accL[1]); accH[1] = ffma2(a1, bv.y, accH[1]);
            accL[2] = ffma2(a2, bv.x, accL[2]); accH[2] = ffma2(a2, bv.y, accH[2]);
            accL[3] = ffma2(a3, bv.x, accL[3]); accH[3] = ffma2(a3, bv.y, accH[3]);
        }
        __syncthreads();
    }
    float4 bvb = *reinterpret_cast<const float4*>(bias + n0 + tn);
#pragma unroll
    for (int i = 0; i < 4; i++) {
        int orow = t * 64 + tm + i;
        float2 lo = unpack2(accL[i]), hi = unpack2(accH[i]);
        float4 o;
        o.x = lo.x + bvb.x; o.y = lo.y + bvb.y;
        o.z = hi.x + bvb.z; o.w = hi.y + bvb.w;
        *reinterpret_cast<float4*>(g_xw + (size_t)orow * G4 + n0 + tn) = o;
    }
}

// ---------------- persistent LSTM layer ----------------
// 128 blocks (one per SM, all resident) x 256 threads. Block owns 4 hidden units
// = 16 z-columns (4 gates x 4 units), all 64 batches.
// Dynamic smem layout: [w2: 512*16 float2 = 64KB][h_s: 2*64*64 float = 32KB][zb: 16*68 = 4.25KB]
#define SMEM_LSTM (512 * 16 * 8 + 2 * 64 * 64 * 4 + 16 * 68 * 4)
__global__ __launch_bounds__(256) void lstm_layer(const float* __restrict__ Wh, int layer) {
    extern __shared__ __align__(16) char smem[];
    float2* w2 = reinterpret_cast<float2*>(smem);                  // [512][16]
    float* h_s = reinterpret_cast<float*>(smem + 512 * 16 * 8);    // [2][64][64]
    float* zb  = h_s + 2 * 64 * 64;                                // [16][68]
    const int tid = threadIdx.x;
    const int j = tid & 15, bg = tid >> 4;           // col-in-block, 4-batch group
    const int u0 = blockIdx.x << 2;
    float* hseq = layer ? g_h2 : g_h1;
    unsigned* bar = &g_bar[layer];
    const int u2 = tid >> 6, b = tid & 63;
    const size_t sidx = (size_t)(u0 + u2) * BB + b;
    float c_reg = 0.f;                               // c state block-private -> register

    // one-time: preload this block's Wh slice, duplicated into f32x2 pairs
    for (int idx = tid; idx < 512 * 16; idx += 256) {
        int k = idx >> 4, jj = idx & 15;
        float v = Wh[(size_t)k * G4 + (jj >> 2) * HH + u0 + (jj & 3)];
        w2[idx] = make_float2(v, v);
    }
    __syncthreads();

    const int colg = (j >> 2) * HH + u0 + (j & 3);
    const unsigned hs0 = (unsigned)__cvta_generic_to_shared(h_s);
    const unsigned hs1 = hs0 + 64 * 64 * 4;

    for (int t = 0; t < TT; t++) {
        const float* hin = g_hT[t & 1];
        float* hout = g_hT[(t & 1) ^ 1];

        // prefetch chunk 0 (16 KB contiguous) into buffer 0
        {
            const float* src = hin + (tid << 2);
            unsigned d = hs0 + (tid << 4);
            cp16(d, src); cp16(d + 4096, src + 1024);
            cp16(d + 8192, src + 2048); cp16(d + 12288, src + 3072);
            asm volatile("cp.async.commit_group;");
        }

        // acc init from xw (packed over batch pairs)
        unsigned long long acc01, acc23;
        {
            const float* xw = g_xw + (size_t)t * (BB * G4) + colg + (size_t)(bg << 2) * G4;
            float z0 = __ldg(xw);
            float z1 = __ldg(xw + G4);
            float z2 = __ldg(xw + 2 * G4);
            float z3 = __ldg(xw + 3 * G4);
            acc01 = pack2(z0, z1);
            acc23 = pack2(z2, z3);
        }

        for (int c = 0; c < 8; c++) {
            if (c < 7) {   // prefetch next chunk into the other buffer
                const float* src = hin + ((c + 1) << 12) + (tid << 2);
                unsigned d = ((c & 1) ? hs0 : hs1) + (tid << 4);
                cp16(d, src); cp16(d + 4096, src + 1024);
                cp16(d + 8192, src + 2048); cp16(d + 12288, src + 3072);
                asm volatile("cp.async.commit_group;");
                asm volatile("cp.async.wait_group 1;");
            } else {
                asm volatile("cp.async.wait_group 0;");
            }
            __syncthreads();
            // h row = 64 floats = 256 B = 16 ulonglong2  (stride fixed: was k*8, bug)
            const ulonglong2* hp =
                reinterpret_cast<const ulonglong2*>(h_s + (c & 1) * 4096 + (bg << 2));
            const unsigned long long* wp =
                reinterpret_cast<const unsigned long long*>(w2 + (c << 6) * 16 + j);
#pragma unroll
            for (int k = 0; k < 64; k++) {
                ulonglong2 hv = hp[k * 16];           // 64 floats/row = 16 ull2
                unsigned long long wv = wp[k * 16];   // 16 f32x2 pairs/row
                acc01 = ffma2(hv.x, wv, acc01);
                acc23 = ffma2(hv.y, wv, acc23);
            }
            __syncthreads();
        }

        // transpose z through smem: zb[j][b], row stride 68
        {
            float2 a01 = unpack2(acc01), a23 = unpack2(acc23);
            *reinterpret_cast<float4*>(zb + j * 68 + (bg << 2)) =
                make_float4(a01.x, a01.y, a23.x, a23.y);
        }
        __syncthreads();
        {
            float zi = zb[u2 * 68 + b], zf = zb[(4 + u2) * 68 + b];
            float zg = zb[(8 + u2) * 68 + b], zo = zb[(12 + u2) * 68 + b];
            float ig = 1.f / (1.f + expf(-zi));
            float fg = 1.f / (1.f + expf(-zf));
            float og = 1.f / (1.f + expf(-zo));
            float gg = tanhf(zg);
            c_reg = fg * c_reg + ig * gg;
            float hn = og * tanhf(c_reg);
            hout[sidx] = hn;
            hseq[(size_t)t * (HH * BB) + sidx] = hn;
        }
        // grid barrier: all blocks finish hout before next step
        __threadfence();
        __syncthreads();
        if (tid == 0) {
            atomicAdd(bar, 1u);
            unsigned target = (unsigned)(t + 1) * 128u;
            while (*(volatile unsigned*)bar < target) { }
        }
        __syncthreads();
    }
}

// ---------------- BN stats (training mode), folded scale/shift, deterministic -------
__global__ __launch_bounds__(256) void bn_stats(int layer, const float* __restrict__ gamma,
                                                const float* __restrict__ beta) {
    const float* h = layer ? g_h2 : g_h1;
    const int kf = blockIdx.x;
    const int tid = threadIdx.x;
    float s = 0.f, ss = 0.f;
    for (int lin = tid; lin < NR; lin += 256) {
        float v = h[(size_t)(lin >> 6) * (HH * BB) + (size_t)kf * BB + (lin & 63)];
        s += v; ss += v * v;
    }
    __shared__ float rs[256], rq[256];
    rs[tid] = s; rq[tid] = ss;
    __syncthreads();
    for (int off = 128; off > 0; off >>= 1) {
        if (tid < off) { rs[tid] += rs[tid + off]; rq[tid] += rq[tid + off]; }
        __syncthreads();
    }
    if (tid == 0) {
        float mean = rs[0] * (1.f / 32768.f);
        float var = rq[0] * (1.f / 32768.f) - mean * mean;
        float rstd = rsqrtf(var + 1e-5f);
        float sc = rstd * gamma[kf];
        g_scale[layer * HH + kf] = sc;
        g_shift[layer * HH + kf] = beta[kf] - mean * sc;
    }
}

// ---------------- Dense head: out[b*T+t] = relu(bn(h2) @ Wd1 + bd1) @ Wd2 + bd2 -----
__global__ __launch_bounds__(256) void dense_out(const float* __restrict__ Wd1,
                                                 const float* __restrict__ bd1,
                                                 const float* __restrict__ Wd2,
                                                 const float* __restrict__ bd2,
                                                 float* __restrict__ out) {
    __shared__ float hs[64][68];
    __shared__ float ws[64][16];
    __shared__ float sp[4][64];
    const int t = blockIdx.x, tid = threadIdx.x;
    const int b = tid & 63, jg = tid >> 6;
    float a0 = 0.f, a1 = 0.f, a2 = 0.f, a3 = 0.f;
    for (int k0 = 0; k0 < HH; k0 += 64) {
#pragma unroll
        for (int i = 0; i < 16; i++) {
            int lin = tid + i * 256; int k = lin >> 6, bb = lin & 63;
            float v = g_h2[(size_t)t * (HH * BB) + (size_t)(k0 + k) * BB + bb];
            hs[k][bb] = v * g_scale[HH + k0 + k] + g_shift[HH + k0 + k];
        }
#pragma unroll
        for (int i = 0; i < 4; i++) {
            int lin = tid + i * 256; int jj = lin & 15, k = lin >> 4;
            ws[k][jj] = Wd1[(size_t)(k0 + k) * 16 + jj];
        }
        __syncthreads();
#pragma unroll
        for (int k = 0; k < 64; k++) {
            float hv = hs[k][b];
            a0 += hv * ws[k][jg * 4 + 0];
            a1 += hv * ws[k][jg * 4 + 1];
            a2 += hv * ws[k][jg * 4 + 2];
            a3 += hv * ws[k][jg * 4 + 3];
        }
        __syncthreads();
    }
    float p = fmaxf(a0 + bd1[jg * 4 + 0], 0.f) * Wd2[jg * 4 + 0]
            + fmaxf(a1 + bd1[jg * 4 + 1], 0.f) * Wd2[jg * 4 + 1]
            + fmaxf(a2 + bd1[jg * 4 + 2], 0.f) * Wd2[jg * 4 + 2]
            + fmaxf(a3 + bd1[jg * 4 + 3], 0.f) * Wd2[jg * 4 + 3];
    sp[jg][b] = p;
    __syncthreads();
    if (tid < 64) {
        out[(size_t)tid * TT + t] = sp[0][tid] + sp[1][tid] + sp[2][tid] + sp[3][tid] + bd2[0];
    }
}

// ---------------- launch (9 graph nodes) ----------------
extern "C" void kernel_launch(void* const* d_in, const int* in_sizes, int n_in,
                              void* d_out, int out_size) {
    const float* x   = (const float*)d_in[0];
    const float* Wx1 = (const float*)d_in[1];
    const float* Wh1 = (const float*)d_in[2];
    const float* b1  = (const float*)d_in[3];
    const float* g1  = (const float*)d_in[4];
    const float* be1 = (const float*)d_in[5];
    const float* Wx2 = (const float*)d_in[6];
    const float* Wh2 = (const float*)d_in[7];
    const float* b2  = (const float*)d_in[8];
    const float* g2  = (const float*)d_in[9];
    const float* be2 = (const float*)d_in[10];
    const float* Wd1 = (const float*)d_in[11];
    const float* bd1 = (const float*)d_in[12];
    const float* Wd2 = (const float*)d_in[13];
    const float* bd2 = (const float*)d_in[14];
    float* out = (float*)d_out;

    static bool attr_set = false;
    if (!attr_set) {
        cudaFuncSetAttribute(lstm_layer, cudaFuncAttributeMaxDynamicSharedMemorySize, SMEM_LSTM);
        attr_set = true;
    }

    zero_state<<<64, 512>>>();
    gemm_xw1<<<dim3(32, 512), 256>>>(x, Wx1, b1);
    lstm_layer<<<128, 256, SMEM_LSTM>>>(Wh1, 0);
    bn_stats<<<512, 256>>>(0, g1, be1);
    gemm_xw2<<<dim3(32, 512), 256>>>(Wx2, b2);
    zero_state<<<64, 512>>>();
    lstm_layer<<<128, 256, SMEM_LSTM>>>(Wh2, 1);
    bn_stats<<<512, 256>>>(1, g2, be2);
    dense_out<<<512, 256>>>(Wd1, bd1, Wd2, bd2, out);
}